// round 15
// baseline (speedup 1.0000x reference)
#include <cuda_runtime.h>
#include <cuda_bf16.h>
#include <cuda_fp16.h>
#include <cstdint>
#include <math.h>

// ---------------- problem dims ----------------
#define NB 64
#define NT 512
#define ND 128
#define NH 512
#define NDS 32
#define NG4 (4 * NH)   // 2048

// ---------------- LSTM config ----------------
#define G 128          // persistent CTAs, 1/SM
#define TPB 256        // 8 warps
#define JPC 4          // hidden units per CTA -> 16 true z-cols (m=16, fp16 W)
// SMEM layout (bytes)
#define H_OFF 0                    // h [2 bufs][4 chunks][64 rows][256B] = 131072
#define WS_OFF 131072              // W' staging [16][1024B] = 16384
#define MB_OFF 147456              // 8 mbarriers (buf x chunk)
#define LSTM_SMEM 147520

__device__ __forceinline__ uint32_t smem_u32(const void* p) {
    uint32_t a;
    asm("{ .reg .u64 t; cvta.to.shared.u64 t, %1; cvt.u32.u64 %0, t; }" : "=r"(a) : "l"(p));
    return a;
}
// fast gate nonlinearities (MUFU-based)
__device__ __forceinline__ float fsig(float x) { return 1.f / (1.f + __expf(-x)); }
__device__ __forceinline__ float ftanh(float x) {
    float ax = fabsf(x);
    float e = __expf(-2.f * ax);
    float r = (1.f - e) / (1.f + e);
    return copysignf(r, x);
}

__device__ __forceinline__ uint4 pack_f16_8(float4 a, float4 b) {
    uint4 r;
    r.x = (uint32_t)__half_as_ushort(__float2half(a.x)) |
          ((uint32_t)__half_as_ushort(__float2half(a.y)) << 16);
    r.y = (uint32_t)__half_as_ushort(__float2half(a.z)) |
          ((uint32_t)__half_as_ushort(__float2half(a.w)) << 16);
    r.z = (uint32_t)__half_as_ushort(__float2half(b.x)) |
          ((uint32_t)__half_as_ushort(__float2half(b.y)) << 16);
    r.w = (uint32_t)__half_as_ushort(__float2half(b.z)) |
          ((uint32_t)__half_as_ushort(__float2half(b.w)) << 16);
    return r;
}

#define LDSM_X4(r0, r1, r2, r3, addr) \
    asm volatile("ldmatrix.sync.aligned.m8n8.x4.shared.b16 {%0,%1,%2,%3}, [%4];" \
        : "=r"(r0), "=r"(r1), "=r"(r2), "=r"(r3) : "r"(addr))

#define MMA_FP16(c, a0, a1, a2, a3, b0, b1) \
    asm volatile("mma.sync.aligned.m16n8k16.row.col.f32.f16.f16.f32 " \
        "{%0,%1,%2,%3}, {%4,%5,%6,%7}, {%8,%9}, {%0,%1,%2,%3};" \
        : "+f"((c)[0]), "+f"((c)[1]), "+f"((c)[2]), "+f"((c)[3]) \
        : "r"(a0), "r"(a1), "r"(a2), "r"(a3), "r"(b0), "r"(b1))

#define CP16(dst, src) \
    asm volatile("cp.async.cg.shared.global [%0], [%1], 16;" :: "r"(dst), "l"(src))
#define CP_COMMIT() asm volatile("cp.async.commit_group;" ::: "memory")
#define CP_WAIT(n)  asm volatile("cp.async.wait_group %0;" :: "n"(n) : "memory")
#define MBARRIER_INIT(mbar, cnt) \
    asm volatile("mbarrier.init.shared.b64 [%0], %1;" :: "r"((uint32_t)(mbar)), "r"((uint32_t)(cnt)) : "memory")
#define MBARRIER_EXPECT_TX(mbar, bytes) \
    asm volatile("mbarrier.arrive.expect_tx.shared.b64 _, [%0], %1;" \
                 :: "r"((uint32_t)(mbar)), "r"((uint32_t)(bytes)) : "memory")
#define BULK_G2S(dst, src, bytes, mbar) \
    asm volatile("cp.async.bulk.shared::cta.global.mbarrier::complete_tx::bytes " \
                 "[%0], [%1], %2, [%3];" \
                 :: "r"((uint32_t)(dst)), "l"(src), "r"((uint32_t)(bytes)), \
                    "r"((uint32_t)(mbar)) : "memory")
#define MBARRIER_WAIT_PARITY(mbar, par) do { \
    uint32_t _m = (uint32_t)(mbar); uint32_t _p = (uint32_t)(par); uint32_t _d; \
    asm volatile("{\n\t.reg .pred p;\n\t" \
        "mbarrier.try_wait.parity.acquire.cta.shared::cta.b64 p, [%1], %2;\n\t" \
        "selp.b32 %0, 1, 0, p;\n\t}" : "=r"(_d) : "r"(_m), "r"(_p) : "memory"); \
    if (!_d) { \
        asm volatile("{\n\t.reg .pred P1;\n\t" \
            "WL_%=:\n\t" \
            "mbarrier.try_wait.parity.acquire.cta.shared::cta.b64 P1, [%0], %1, 0x989680;\n\t" \
            "@P1 bra.uni WD_%=;\n\t" \
            "bra.uni WL_%=;\n\t" \
            "WD_%=:\n\t}" :: "r"(_m), "r"(_p) : "memory"); \
    } } while (0)

// ---------------- global scratch ----------------
// h (fp16) in the exact swizzled SMEM image: [buf][chunk(k128)][row=batch][256B]
__device__ __align__(128) uint8_t g_hb[2][4][64][256];
__device__ __half g_wt[NG4][ND];                // wk transposed (fp16)
__device__ float g_xw[NT][NH][NB][4];           // x@Wk + bias, [t][j][b][gate]
__device__ float g_hs[NT][NH][NB];              // hidden states for dense
__device__ unsigned int g_cbar[4 * 32];         // per-chunk monotonic counters

__global__ void init_kernel() {
    int idx = blockIdx.x * blockDim.x + threadIdx.x;
    if (idx < 4 * 32) g_cbar[idx] = 0u;
    uint32_t* p = reinterpret_cast<uint32_t*>(&g_hb[0][0][0][0]);
    for (int i = idx; i < (int)(sizeof(g_hb) / 4); i += gridDim.x * blockDim.x)
        p[i] = 0u;
}

// ---- one-time: transpose + fp16 convert of wk ----
__global__ void wbf_kernel(const float* __restrict__ wk) {
    int n = blockIdx.x;          // 0..2047
    int k = threadIdx.x;         // 0..127
    g_wt[n][k] = __float2half(wk[(size_t)k * NG4 + n]);
}

// =====================================================================
// XW kernel (fp16): g_xw[t][j][b][gate] = x@wk + bias
// =====================================================================
#define XA_OFF 0           // [64][256B] = 16384
#define XB_OFF 16384       // [64][256B] = 16384
#define XZ_OFF 32768       // zb[64][65] f32 = 16640
#define XW_SMEM 49408

__global__ void __launch_bounds__(256, 1) xw_kernel(
    const float* __restrict__ x, const float* __restrict__ bias)
{
    extern __shared__ char smem[];
    const uint32_t sbu = smem_u32(smem);
    float* zb = reinterpret_cast<float*>(smem + XZ_OFF);
    const int tid = threadIdx.x, wid = tid >> 5, lane = tid & 31;
    const int t = blockIdx.x;
    const int s7 = lane & 7;

    // A staging: x fp16, 64 rows (batch) x 256B (k=128)
    for (int i = tid; i < 64 * 16; i += 256) {
        int b = i >> 4, cs = i & 15;
        const float4* xp = reinterpret_cast<const float4*>(
            x + ((size_t)b * NT + t) * ND + cs * 8);
        *reinterpret_cast<uint4*>(smem + XA_OFF + b * 256 + ((cs ^ (b & 7)) << 4))
            = pack_f16_8(xp[0], xp[1]);
    }
    __syncthreads();

    const int mslice = wid & 3, whalf = wid >> 2;
    uint32_t ar[8][4];
    {
        int row8 = ((lane >> 3) & 1) * 8 + s7;
        int acb = lane >> 4;
        #pragma unroll
        for (int ks = 0; ks < 8; ks++) {
            int row = mslice * 16 + row8;
            uint32_t addr = sbu + XA_OFF + row * 256 +
                (((ks * 2 + acb) ^ (row & 7)) << 4);
            LDSM_X4(ar[ks][0], ar[ks][1], ar[ks][2], ar[ks][3], addr);
        }
    }

    const int browl = ((lane >> 4) << 3) + s7;
    const int bcb = (lane >> 3) & 1;

    for (int cb = 0; cb < 32; cb++) {
        #pragma unroll
        for (int it = 0; it < 4; it++) {
            int i = it * 256 + tid;
            int row = i >> 4, cpi = i & 15;
            const __half* src = &g_wt[cb * 64 + row][cpi * 8];
            uint32_t dst = sbu + XB_OFF + row * 256 + ((cpi ^ (row & 7)) << 4);
            CP16(dst, src);
        }
        CP_COMMIT();
        CP_WAIT(0);
        __syncthreads();

        float acc[4][4];
        #pragma unroll
        for (int nf = 0; nf < 4; nf++)
            #pragma unroll
            for (int q = 0; q < 4; q++) acc[nf][q] = 0.f;

        #pragma unroll
        for (int ks = 0; ks < 8; ks++) {
            #pragma unroll
            for (int q = 0; q < 2; q++) {
                int rowb = whalf * 32 + q * 16 + browl;
                uint32_t baddr = sbu + XB_OFF + rowb * 256 +
                    (((ks * 2 + bcb) ^ s7) << 4);
                uint32_t b0, b1, b2, b3;
                LDSM_X4(b0, b1, b2, b3, baddr);
                MMA_FP16(acc[2 * q],     ar[ks][0], ar[ks][1], ar[ks][2], ar[ks][3], b0, b1);
                MMA_FP16(acc[2 * q + 1], ar[ks][0], ar[ks][1], ar[ks][2], ar[ks][3], b2, b3);
            }
        }

        // epilogue -> zb[batch][col]
        #pragma unroll
        for (int nf = 0; nf < 4; nf++) {
            int m = mslice * 16 + (lane >> 2);
            int c = whalf * 32 + (nf >> 1) * 16 + (nf & 1) * 8 + 2 * (lane & 3);
            zb[(size_t)m * 65 + c]           = acc[nf][0];
            zb[(size_t)m * 65 + c + 1]       = acc[nf][1];
            zb[(size_t)(m + 8) * 65 + c]     = acc[nf][2];
            zb[(size_t)(m + 8) * 65 + c + 1] = acc[nf][3];
        }
        __syncthreads();

        for (int i = tid; i < 64 * 64; i += 256) {
            int b = i & 63, cl = i >> 6;
            int col = cb * 64 + cl;
            int gate = col >> 9, j = col & (NH - 1);
            g_xw[t][j][b][gate] = zb[(size_t)b * 65 + cl] + bias[col];
        }
        __syncthreads();
    }
}

// =====================================================================
// Persistent LSTM — warp-dataflow: no per-step __syncthreads.
// Double-buffered SMEM h (2x64KB) + 8 mbarriers (buf x chunk).
// Per-warp publish (syncwarp + lane0 red.release), counter target 256*t.
// =====================================================================
__global__ void __launch_bounds__(TPB, 1) lstm_kernel(
    const float* __restrict__ wr,
    float* __restrict__ out_h, float* __restrict__ out_c)
{
    extern __shared__ char smem[];
    const uint32_t sbu = smem_u32(smem);

    const int tid = threadIdx.x;
    const int wid = tid >> 5, lane = tid & 31;
    const int j0 = blockIdx.x * JPC;
    const int s7 = lane & 7;
    const int mychunk = blockIdx.x >> 5;

    if (tid == 0) {
        #pragma unroll
        for (int c = 0; c < 8; c++) MBARRIER_INIT(sbu + MB_OFF + 8 * c, 1);
    }

    // ---- W' staging (fp16): rows m 0-15 = col(gate*4+jj) ----
    for (int i = tid; i < 16 * NH; i += TPB) {
        int m = i & 15, k = i >> 4;
        int gate = m >> 2, jj = m & 3;
        float w = wr[(size_t)k * NG4 + gate * NH + j0 + jj];
        *reinterpret_cast<uint16_t*>(smem + WS_OFF + m * 1024 +
            ((((k >> 3) ^ (m & 7)) << 4) | ((k & 7) << 1))) =
            __half_as_ushort(__float2half(w));
    }
    __syncthreads();

    // ---- a-frags: full k=512, m16 ----
    uint32_t ar[32][4];
    {
        int row = ((lane >> 3) & 1) * 8 + s7;
        int acb = lane >> 4;
        uint32_t rbase = sbu + WS_OFF + row * 1024;
        #pragma unroll
        for (int ks = 0; ks < 32; ks++) {
            int chunk = ks * 2 + acb;
            LDSM_X4(ar[ks][0], ar[ks][1], ar[ks][2], ar[ks][3],
                    rbase + ((chunk ^ (row & 7)) << 4));
        }
    }
    __syncthreads();

    // this thread's gate identity: batch = 8*wid + bl, hidden jj
    const int bl = lane & 7;
    const int jj = lane >> 3;
    const int gb = wid * 8 + bl;
    const int jrow = j0 + jj;
    float c_state = 0.f;

    const int bg4 = lane >> 3;
    const uint32_t browoff = (wid * 8 + s7) * 256;

    // gate shuffle sources
    const int lsrc1 = jj * 4 + (bl >> 1);
    const int lsrc2 = lsrc1 + 16;
    const bool bodd = (bl & 1) != 0;

    // producer h-write address (pre-swizzled fp16 image)
    const int kq = jrow & 127;
    const size_t poff = (size_t)(jrow >> 7) * 16384 + (size_t)gb * 256 +
                        (((kq >> 3) ^ (gb & 7)) << 4) + (kq & 7) * 2;

    for (int t = 0; t < NT; t++) {
        // prefetch xw (one LDG.128; consumed at gates)
        float4 xwv;
        {
            const float4* xp = reinterpret_cast<const float4*>(&g_xw[t][jrow][gb][0]);
            xwv = __ldcg(xp);
        }

        const int buf = t & 1;
        const uint32_t hbase_s = sbu + H_OFF + buf * 65536;
        const uint32_t mbbase = sbu + MB_OFF + buf * 32;
        const uint32_t par = (t >> 1) & 1;

        // ---- parallel poll + per-chunk bulk copy (warp 0, lanes 0-3) ----
        if (wid == 0 && lane < 4) {
            const unsigned int tgt = 256u * (unsigned int)t;
            const unsigned int* cp = &g_cbar[lane * 32];
            const uint8_t* hsrc = &g_hb[buf][lane][0][0];
            uint32_t mb = mbbase + 8 * lane;
            uint32_t dsts = hbase_s + lane * 16384;
            bool issued = false;
            for (;;) {
                unsigned int cur;
                asm volatile("ld.global.acquire.gpu.u32 %0, [%1];"
                             : "=r"(cur) : "l"(cp));
                bool ready = cur >= tgt;
                if (ready && !issued) {
                    MBARRIER_EXPECT_TX(mb, 16384);
                    BULK_G2S(dsts, hsrc, 16384, mb);
                    issued = true;
                }
                if (__all_sync(0x0000000Fu, ready)) break;
            }
        }

        float acc[4];
        acc[0] = acc[1] = acc[2] = acc[3] = 0.f;

        // ---- chunk-ordered MMA: per kk2 one LDSM.x4 (n8 k32) + 2 MMA ----
        #pragma unroll
        for (int c = 0; c < 4; c++) {
            MBARRIER_WAIT_PARITY(mbbase + 8 * c, par);
            uint32_t base0 = hbase_s + c * 16384 + browoff;
            #pragma unroll
            for (int kk2 = 0; kk2 < 4; kk2++) {
                int ks = c * 8 + kk2 * 2;
                uint32_t off = (((kk2 * 4 + bg4) ^ s7) << 4);
                uint32_t b0, b1, b2, b3;
                LDSM_X4(b0, b1, b2, b3, base0 + off);
                MMA_FP16(acc, ar[ks][0],     ar[ks][1],     ar[ks][2],     ar[ks][3],     b0, b1);
                MMA_FP16(acc, ar[ks + 1][0], ar[ks + 1][1], ar[ks + 1][2], ar[ks + 1][3], b2, b3);
            }
        }

        // ---- gates fully in-warp: 8 shuffles transpose the z tile ----
        float hv;
        {
            float v0 = __shfl_sync(0xffffffffu, acc[0], lsrc1);
            float v1 = __shfl_sync(0xffffffffu, acc[1], lsrc1);
            float v2 = __shfl_sync(0xffffffffu, acc[2], lsrc1);
            float v3 = __shfl_sync(0xffffffffu, acc[3], lsrc1);
            float w0 = __shfl_sync(0xffffffffu, acc[0], lsrc2);
            float w1 = __shfl_sync(0xffffffffu, acc[1], lsrc2);
            float w2 = __shfl_sync(0xffffffffu, acc[2], lsrc2);
            float w3 = __shfl_sync(0xffffffffu, acc[3], lsrc2);
            float z0 = xwv.x + (bodd ? v1 : v0);
            float z1 = xwv.y + (bodd ? w1 : w0);
            float z2 = xwv.z + (bodd ? v3 : v2);
            float z3 = xwv.w + (bodd ? w3 : w2);

            float ig = fsig(z0);
            float fg = fsig(z1);
            float gv = ftanh(z2);
            float og = fsig(z3);
            c_state = fg * c_state + ig * gv;
            hv = og * ftanh(c_state);
            uint8_t* hdst = &g_hb[(t + 1) & 1][0][0][0];
            *reinterpret_cast<uint16_t*>(hdst + poff) =
                __half_as_ushort(__float2half(hv));
        }
        __syncwarp();

        // ---- per-warp publish: lane0 release-add (covers warp via syncwarp) ----
        if (t < NT - 1 && lane == 0) {
            asm volatile("red.release.gpu.global.add.u32 [%0], %1;"
                         :: "l"(&g_cbar[mychunk * 32]), "r"(1u) : "memory");
        }

        // ---- off-critical-path: hs store for dense + final outputs ----
        g_hs[t][jrow][gb] = hv;
        if (t == NT - 1) {
            out_h[(size_t)gb * NH + jrow] = hv;
            out_c[(size_t)gb * NH + jrow] = c_state;
        }
    }
}

// ---------------- Dense(32, tanh) over all timesteps ----------------
#define DTPB 256
__global__ void __launch_bounds__(DTPB, 1) dense_kernel(
    const float* __restrict__ dw, const float* __restrict__ db,
    float* __restrict__ out)
{
    extern __shared__ float smemf[];
    float* hsm = smemf;
    float* wsm = smemf + NH * NB;
    int t = blockIdx.x, tid = threadIdx.x;
    {
        const float4* src = reinterpret_cast<const float4*>(&g_hs[t][0][0]);
        float4* dst = reinterpret_cast<float4*>(hsm);
        for (int i = tid; i < NH * NB / 4; i += DTPB) dst[i] = src[i];
        const float4* ws = reinterpret_cast<const float4*>(dw);
        float4* wd = reinterpret_cast<float4*>(wsm);
        for (int i = tid; i < NH * NDS / 4; i += DTPB) wd[i] = ws[i];
    }
    __syncthreads();

    int bg = tid & 15, dg = tid >> 4;
    float acc[4][2];
    #pragma unroll
    for (int bi = 0; bi < 4; bi++) { acc[bi][0] = 0.f; acc[bi][1] = 0.f; }
    #pragma unroll 4
    for (int k = 0; k < NH; k++) {
        float4 hv = *reinterpret_cast<const float4*>(&hsm[k * NB + bg * 4]);
        float2 wv = *reinterpret_cast<const float2*>(&wsm[k * NDS + dg * 2]);
        float hvv[4] = {hv.x, hv.y, hv.z, hv.w};
        #pragma unroll
        for (int bi = 0; bi < 4; bi++) {
            acc[bi][0] += hvv[bi] * wv.x;
            acc[bi][1] += hvv[bi] * wv.y;
        }
    }
    float b0 = db[dg * 2], b1 = db[dg * 2 + 1];
    #pragma unroll
    for (int bi = 0; bi < 4; bi++) {
        int b = bg * 4 + bi;
        size_t base = (size_t)b * NT * NDS + (size_t)t * NDS + dg * 2;
        out[base]     = tanhf(acc[bi][0] + b0);
        out[base + 1] = tanhf(acc[bi][1] + b1);
    }
}

#define DENSE_SMEM ((NH * NB + NH * NDS) * 4)

extern "C" void kernel_launch(void* const* d_in, const int* in_sizes, int n_in,
                              void* d_out, int out_size) {
    const float* x    = (const float*)d_in[0];
    const float* wk   = (const float*)d_in[1];
    const float* wr   = (const float*)d_in[2];
    const float* bias = (const float*)d_in[3];
    const float* dw   = (const float*)d_in[4];
    const float* db   = (const float*)d_in[5];
    float* out   = (float*)d_out;
    float* out_h = out + (size_t)NB * NT * NDS;
    float* out_c = out_h + (size_t)NB * NH;

    cudaFuncSetAttribute(xw_kernel,
                         cudaFuncAttributeMaxDynamicSharedMemorySize, XW_SMEM);
    cudaFuncSetAttribute(lstm_kernel,
                         cudaFuncAttributeMaxDynamicSharedMemorySize, LSTM_SMEM);
    cudaFuncSetAttribute(dense_kernel,
                         cudaFuncAttributeMaxDynamicSharedMemorySize, DENSE_SMEM);

    init_kernel<<<64, 256>>>();                          // 0
    wbf_kernel<<<NG4, ND>>>(wk);                         // 1
    xw_kernel<<<NT, 256, XW_SMEM>>>(x, bias);            // 2
    lstm_kernel<<<G, TPB, LSTM_SMEM>>>(wr, out_h, out_c);// 3  <- profiled slot
    dense_kernel<<<NT, DTPB, DENSE_SMEM>>>(dw, db, out); // 4
}

// round 16
// speedup vs baseline: 1.1196x; 1.1196x over previous
#include <cuda_runtime.h>
#include <cuda_bf16.h>
#include <cuda_fp16.h>
#include <cstdint>
#include <math.h>

// ---------------- problem dims ----------------
#define NB 64
#define NT 512
#define ND 128
#define NH 512
#define NDS 32
#define NG4 (4 * NH)   // 2048

// ---------------- LSTM config (R14 structure) ----------------
#define G 128          // persistent CTAs, 1/SM
#define TPB 256        // 8 warps
#define JPC 4          // hidden units per CTA -> 16 true z-cols (m=16, fp16 W)
// SMEM layout (bytes)
#define H_OFF 0                    // h [4 chunks][64 rows][256B] = 65536
#define WS_OFF 65536               // W' staging [16][1024B] = 16384
#define MB_OFF 81920               // 4 mbarriers
#define LSTM_SMEM 81984

__device__ __forceinline__ uint32_t smem_u32(const void* p) {
    uint32_t a;
    asm("{ .reg .u64 t; cvta.to.shared.u64 t, %1; cvt.u32.u64 %0, t; }" : "=r"(a) : "l"(p));
    return a;
}
// fast gate nonlinearities (MUFU-based)
__device__ __forceinline__ float fsig(float x) { return 1.f / (1.f + __expf(-x)); }
__device__ __forceinline__ float ftanh(float x) {
    float ax = fabsf(x);
    float e = __expf(-2.f * ax);
    float r = (1.f - e) / (1.f + e);
    return copysignf(r, x);
}

__device__ __forceinline__ uint4 pack_f16_8(float4 a, float4 b) {
    uint4 r;
    r.x = (uint32_t)__half_as_ushort(__float2half(a.x)) |
          ((uint32_t)__half_as_ushort(__float2half(a.y)) << 16);
    r.y = (uint32_t)__half_as_ushort(__float2half(a.z)) |
          ((uint32_t)__half_as_ushort(__float2half(a.w)) << 16);
    r.z = (uint32_t)__half_as_ushort(__float2half(b.x)) |
          ((uint32_t)__half_as_ushort(__float2half(b.y)) << 16);
    r.w = (uint32_t)__half_as_ushort(__float2half(b.z)) |
          ((uint32_t)__half_as_ushort(__float2half(b.w)) << 16);
    return r;
}

#define LDSM_X4(r0, r1, r2, r3, addr) \
    asm volatile("ldmatrix.sync.aligned.m8n8.x4.shared.b16 {%0,%1,%2,%3}, [%4];" \
        : "=r"(r0), "=r"(r1), "=r"(r2), "=r"(r3) : "r"(addr))

#define MMA_FP16(c, a0, a1, a2, a3, b0, b1) \
    asm volatile("mma.sync.aligned.m16n8k16.row.col.f32.f16.f16.f32 " \
        "{%0,%1,%2,%3}, {%4,%5,%6,%7}, {%8,%9}, {%0,%1,%2,%3};" \
        : "+f"((c)[0]), "+f"((c)[1]), "+f"((c)[2]), "+f"((c)[3]) \
        : "r"(a0), "r"(a1), "r"(a2), "r"(a3), "r"(b0), "r"(b1))

#define CP16(dst, src) \
    asm volatile("cp.async.cg.shared.global [%0], [%1], 16;" :: "r"(dst), "l"(src))
#define CP_COMMIT() asm volatile("cp.async.commit_group;" ::: "memory")
#define CP_WAIT(n)  asm volatile("cp.async.wait_group %0;" :: "n"(n) : "memory")
#define MBARRIER_INIT(mbar, cnt) \
    asm volatile("mbarrier.init.shared.b64 [%0], %1;" :: "r"((uint32_t)(mbar)), "r"((uint32_t)(cnt)) : "memory")
#define MBARRIER_EXPECT_TX(mbar, bytes) \
    asm volatile("mbarrier.arrive.expect_tx.shared.b64 _, [%0], %1;" \
                 :: "r"((uint32_t)(mbar)), "r"((uint32_t)(bytes)) : "memory")
#define BULK_G2S(dst, src, bytes, mbar) \
    asm volatile("cp.async.bulk.shared::cta.global.mbarrier::complete_tx::bytes " \
                 "[%0], [%1], %2, [%3];" \
                 :: "r"((uint32_t)(dst)), "l"(src), "r"((uint32_t)(bytes)), \
                    "r"((uint32_t)(mbar)) : "memory")
#define MBARRIER_WAIT_PARITY(mbar, par) do { \
    uint32_t _m = (uint32_t)(mbar); uint32_t _p = (uint32_t)(par); uint32_t _d; \
    asm volatile("{\n\t.reg .pred p;\n\t" \
        "mbarrier.try_wait.parity.acquire.cta.shared::cta.b64 p, [%1], %2;\n\t" \
        "selp.b32 %0, 1, 0, p;\n\t}" : "=r"(_d) : "r"(_m), "r"(_p) : "memory"); \
    if (!_d) { \
        asm volatile("{\n\t.reg .pred P1;\n\t" \
            "WL_%=:\n\t" \
            "mbarrier.try_wait.parity.acquire.cta.shared::cta.b64 P1, [%0], %1, 0x989680;\n\t" \
            "@P1 bra.uni WD_%=;\n\t" \
            "bra.uni WL_%=;\n\t" \
            "WD_%=:\n\t}" :: "r"(_m), "r"(_p) : "memory"); \
    } } while (0)

// ---------------- global scratch ----------------
// h (fp16) in the exact swizzled SMEM image: [buf][chunk(k128)][row=batch][256B]
__device__ __align__(128) uint8_t g_hb[2][4][64][256];
__device__ __half g_wt[NG4][ND];                // wk transposed (fp16)
__device__ float g_xw[NT][NH][NB][4];           // x@Wk + bias, [t][j][b][gate]
__device__ __half g_hs[NT][NH][NB];             // hidden states for dense (fp16)
__device__ unsigned int g_cbar[4 * 32];         // per-chunk monotonic counters

__global__ void init_kernel() {
    int idx = blockIdx.x * blockDim.x + threadIdx.x;
    if (idx < 4 * 32) g_cbar[idx] = 0u;
    uint32_t* p = reinterpret_cast<uint32_t*>(&g_hb[0][0][0][0]);
    for (int i = idx; i < (int)(sizeof(g_hb) / 4); i += gridDim.x * blockDim.x)
        p[i] = 0u;
}

// ---- one-time: transpose + fp16 convert of wk ----
__global__ void wbf_kernel(const float* __restrict__ wk) {
    int n = blockIdx.x;          // 0..2047
    int k = threadIdx.x;         // 0..127
    g_wt[n][k] = __float2half(wk[(size_t)k * NG4 + n]);
}

// =====================================================================
// XW kernel (fp16, 2-stage pipelined B): g_xw[t][j][b][gate] = x@wk + bias
// =====================================================================
#define XA_OFF 0           // [64][256B] = 16384
#define XB_OFF 16384       // 2 stages x 16384 = 32768
#define XZ_OFF 49152       // zb[64][65] f32 = 16640
#define XW_SMEM 65792

__global__ void __launch_bounds__(256, 1) xw_kernel(
    const float* __restrict__ x, const float* __restrict__ bias)
{
    extern __shared__ char smem[];
    const uint32_t sbu = smem_u32(smem);
    float* zb = reinterpret_cast<float*>(smem + XZ_OFF);
    const int tid = threadIdx.x, wid = tid >> 5, lane = tid & 31;
    const int t = blockIdx.x;
    const int s7 = lane & 7;

    // A staging: x fp16, 64 rows (batch) x 256B (k=128)
    for (int i = tid; i < 64 * 16; i += 256) {
        int b = i >> 4, cs = i & 15;
        const float4* xp = reinterpret_cast<const float4*>(
            x + ((size_t)b * NT + t) * ND + cs * 8);
        *reinterpret_cast<uint4*>(smem + XA_OFF + b * 256 + ((cs ^ (b & 7)) << 4))
            = pack_f16_8(xp[0], xp[1]);
    }
    __syncthreads();

    const int mslice = wid & 3, whalf = wid >> 2;
    uint32_t ar[8][4];
    {
        int row8 = ((lane >> 3) & 1) * 8 + s7;
        int acb = lane >> 4;
        #pragma unroll
        for (int ks = 0; ks < 8; ks++) {
            int row = mslice * 16 + row8;
            uint32_t addr = sbu + XA_OFF + row * 256 +
                (((ks * 2 + acb) ^ (row & 7)) << 4);
            LDSM_X4(ar[ks][0], ar[ks][1], ar[ks][2], ar[ks][3], addr);
        }
    }

    const int browl = ((lane >> 4) << 3) + s7;
    const int bcb = (lane >> 3) & 1;

    // prefetch stage 0
    {
        #pragma unroll
        for (int it = 0; it < 4; it++) {
            int i = it * 256 + tid;
            int row = i >> 4, cpi = i & 15;
            const __half* src = &g_wt[row][cpi * 8];
            uint32_t dst = sbu + XB_OFF + row * 256 + ((cpi ^ (row & 7)) << 4);
            CP16(dst, src);
        }
        CP_COMMIT();
    }

    for (int cb = 0; cb < 32; cb++) {
        // prefetch next stage
        if (cb + 1 < 32) {
            uint32_t stg = ((cb + 1) & 1) * 16384;
            #pragma unroll
            for (int it = 0; it < 4; it++) {
                int i = it * 256 + tid;
                int row = i >> 4, cpi = i & 15;
                const __half* src = &g_wt[(cb + 1) * 64 + row][cpi * 8];
                uint32_t dst = sbu + XB_OFF + stg + row * 256 + ((cpi ^ (row & 7)) << 4);
                CP16(dst, src);
            }
            CP_COMMIT();
            CP_WAIT(1);
        } else {
            CP_WAIT(0);
        }
        __syncthreads();

        const uint32_t xb = sbu + XB_OFF + (cb & 1) * 16384;
        float acc[4][4];
        #pragma unroll
        for (int nf = 0; nf < 4; nf++)
            #pragma unroll
            for (int q = 0; q < 4; q++) acc[nf][q] = 0.f;

        #pragma unroll
        for (int ks = 0; ks < 8; ks++) {
            #pragma unroll
            for (int q = 0; q < 2; q++) {
                int rowb = whalf * 32 + q * 16 + browl;
                uint32_t baddr = xb + rowb * 256 + (((ks * 2 + bcb) ^ s7) << 4);
                uint32_t b0, b1, b2, b3;
                LDSM_X4(b0, b1, b2, b3, baddr);
                MMA_FP16(acc[2 * q],     ar[ks][0], ar[ks][1], ar[ks][2], ar[ks][3], b0, b1);
                MMA_FP16(acc[2 * q + 1], ar[ks][0], ar[ks][1], ar[ks][2], ar[ks][3], b2, b3);
            }
        }

        // epilogue -> zb[batch][col]
        #pragma unroll
        for (int nf = 0; nf < 4; nf++) {
            int m = mslice * 16 + (lane >> 2);
            int c = whalf * 32 + (nf >> 1) * 16 + (nf & 1) * 8 + 2 * (lane & 3);
            zb[(size_t)m * 65 + c]           = acc[nf][0];
            zb[(size_t)m * 65 + c + 1]       = acc[nf][1];
            zb[(size_t)(m + 8) * 65 + c]     = acc[nf][2];
            zb[(size_t)(m + 8) * 65 + c + 1] = acc[nf][3];
        }
        __syncthreads();

        for (int i = tid; i < 64 * 64; i += 256) {
            int b = i & 63, cl = i >> 6;
            int col = cb * 64 + cl;
            int gate = col >> 9, j = col & (NH - 1);
            g_xw[t][j][b][gate] = zb[(size_t)b * 65 + cl] + bias[col];
        }
        __syncthreads();
    }
}

// =====================================================================
// Persistent LSTM (R14 structure) — fp16 W (m16), 8 warps x (m16 x n8),
// in-warp gates, single-buffer SMEM h, 4 mbarriers, CTA-level publish.
// =====================================================================
__global__ void __launch_bounds__(TPB, 1) lstm_kernel(
    const float* __restrict__ wr,
    float* __restrict__ out_h, float* __restrict__ out_c)
{
    extern __shared__ char smem[];
    const uint32_t sbu = smem_u32(smem);

    const int tid = threadIdx.x;
    const int wid = tid >> 5, lane = tid & 31;
    const int j0 = blockIdx.x * JPC;
    const int s7 = lane & 7;
    const int mychunk = blockIdx.x >> 5;

    if (tid == 0) {
        #pragma unroll
        for (int c = 0; c < 4; c++) MBARRIER_INIT(sbu + MB_OFF + 8 * c, 1);
    }

    // ---- W' staging (fp16): rows m 0-15 = col(gate*4+jj) ----
    for (int i = tid; i < 16 * NH; i += TPB) {
        int m = i & 15, k = i >> 4;
        int gate = m >> 2, jj = m & 3;
        float w = wr[(size_t)k * NG4 + gate * NH + j0 + jj];
        *reinterpret_cast<uint16_t*>(smem + WS_OFF + m * 1024 +
            ((((k >> 3) ^ (m & 7)) << 4) | ((k & 7) << 1))) =
            __half_as_ushort(__float2half(w));
    }
    __syncthreads();

    // ---- a-frags: full k=512, m16 ----
    uint32_t ar[32][4];
    {
        int row = ((lane >> 3) & 1) * 8 + s7;
        int acb = lane >> 4;
        uint32_t rbase = sbu + WS_OFF + row * 1024;
        #pragma unroll
        for (int ks = 0; ks < 32; ks++) {
            int chunk = ks * 2 + acb;
            LDSM_X4(ar[ks][0], ar[ks][1], ar[ks][2], ar[ks][3],
                    rbase + ((chunk ^ (row & 7)) << 4));
        }
    }
    __syncthreads();

    // this thread's gate identity: batch = 8*wid + bl, hidden jj
    const int bl = lane & 7;
    const int jj = lane >> 3;
    const int gb = wid * 8 + bl;
    const int jrow = j0 + jj;
    float c_state = 0.f;

    const int bg4 = lane >> 3;
    const uint32_t bbase = sbu + H_OFF + (wid * 8 + s7) * 256;

    // gate shuffle sources
    const int lsrc1 = jj * 4 + (bl >> 1);
    const int lsrc2 = lsrc1 + 16;
    const bool bodd = (bl & 1) != 0;

    // producer h-write address (pre-swizzled fp16 image)
    const int kq = jrow & 127;
    const size_t poff = (size_t)(jrow >> 7) * 16384 + (size_t)gb * 256 +
                        (((kq >> 3) ^ (gb & 7)) << 4) + (kq & 7) * 2;

    for (int t = 0; t < NT; t++) {
        // prefetch xw (one LDG.128; consumed at gates)
        float4 xwv;
        {
            const float4* xp = reinterpret_cast<const float4*>(&g_xw[t][jrow][gb][0]);
            xwv = __ldcg(xp);
        }

        const int buf = t & 1;
        // ---- parallel poll + per-chunk bulk copy (warp 0, lanes 0-3) ----
        if (wid == 0 && lane < 4) {
            const unsigned int tgt = 32u * (unsigned int)t;
            const unsigned int* cp = &g_cbar[lane * 32];
            const uint8_t* hsrc = &g_hb[buf][lane][0][0];
            uint32_t mb = sbu + MB_OFF + 8 * lane;
            uint32_t dsts = sbu + H_OFF + lane * 16384;
            bool issued = false;
            for (;;) {
                unsigned int cur;
                asm volatile("ld.global.acquire.gpu.u32 %0, [%1];"
                             : "=r"(cur) : "l"(cp));
                bool ready = cur >= tgt;
                if (ready && !issued) {
                    MBARRIER_EXPECT_TX(mb, 16384);
                    BULK_G2S(dsts, hsrc, 16384, mb);
                    issued = true;
                }
                if (__all_sync(0x0000000Fu, ready)) break;
            }
        }

        float acc[4];
        acc[0] = acc[1] = acc[2] = acc[3] = 0.f;

        // ---- chunk-ordered MMA: per kk2 one LDSM.x4 (n8 k32) + 2 MMA ----
        #pragma unroll
        for (int c = 0; c < 4; c++) {
            MBARRIER_WAIT_PARITY(sbu + MB_OFF + 8 * c, t & 1);
            uint32_t base0 = bbase + c * 16384;
            #pragma unroll
            for (int kk2 = 0; kk2 < 4; kk2++) {
                int ks = c * 8 + kk2 * 2;
                uint32_t off = (((kk2 * 4 + bg4) ^ s7) << 4);
                uint32_t b0, b1, b2, b3;
                LDSM_X4(b0, b1, b2, b3, base0 + off);
                MMA_FP16(acc, ar[ks][0],     ar[ks][1],     ar[ks][2],     ar[ks][3],     b0, b1);
                MMA_FP16(acc, ar[ks + 1][0], ar[ks + 1][1], ar[ks + 1][2], ar[ks + 1][3], b2, b3);
            }
        }

        // ---- gates fully in-warp: 8 shuffles transpose the z tile ----
        float hv;
        {
            float v0 = __shfl_sync(0xffffffffu, acc[0], lsrc1);
            float v1 = __shfl_sync(0xffffffffu, acc[1], lsrc1);
            float v2 = __shfl_sync(0xffffffffu, acc[2], lsrc1);
            float v3 = __shfl_sync(0xffffffffu, acc[3], lsrc1);
            float w0 = __shfl_sync(0xffffffffu, acc[0], lsrc2);
            float w1 = __shfl_sync(0xffffffffu, acc[1], lsrc2);
            float w2 = __shfl_sync(0xffffffffu, acc[2], lsrc2);
            float w3 = __shfl_sync(0xffffffffu, acc[3], lsrc2);
            float z0 = xwv.x + (bodd ? v1 : v0);
            float z1 = xwv.y + (bodd ? w1 : w0);
            float z2 = xwv.z + (bodd ? v3 : v2);
            float z3 = xwv.w + (bodd ? w3 : w2);

            float ig = fsig(z0);
            float fg = fsig(z1);
            float gv = ftanh(z2);
            float og = fsig(z3);
            c_state = fg * c_state + ig * gv;
            hv = og * ftanh(c_state);
            uint8_t* hdst = &g_hb[(t + 1) & 1][0][0][0];
            *reinterpret_cast<uint16_t*>(hdst + poff) =
                __half_as_ushort(__float2half(hv));
        }
        __syncthreads();

        // ---- publish (release atomic covers all h stores via syncthreads) ----
        if (t < NT - 1 && tid == 0) {
            asm volatile("red.release.gpu.global.add.u32 [%0], %1;"
                         :: "l"(&g_cbar[mychunk * 32]), "r"(1u) : "memory");
        }

        // ---- off-critical-path: hs store for dense + final outputs ----
        g_hs[t][jrow][gb] = __float2half(hv);
        if (t == NT - 1) {
            out_h[(size_t)gb * NH + jrow] = hv;
            out_c[(size_t)gb * NH + jrow] = c_state;
        }
    }
}

// ---------------- Dense(32, tanh) over all timesteps ----------------
#define DTPB 256
__global__ void __launch_bounds__(DTPB, 1) dense_kernel(
    const float* __restrict__ dw, const float* __restrict__ db,
    float* __restrict__ out)
{
    extern __shared__ float smemf[];
    float* hsm = smemf;                 // [NH][NB] fp32
    float* wsm = smemf + NH * NB;       // [NH][NDS]
    int t = blockIdx.x, tid = threadIdx.x;
    {
        const uint4* src = reinterpret_cast<const uint4*>(&g_hs[t][0][0]);
        for (int i = tid; i < NH * NB / 8; i += DTPB) {
            uint4 v = src[i];
            const __half* hp = reinterpret_cast<const __half*>(&v);
            float* dst = hsm + (size_t)i * 8;
            #pragma unroll
            for (int q = 0; q < 8; q++) dst[q] = __half2float(hp[q]);
        }
        const float4* ws = reinterpret_cast<const float4*>(dw);
        float4* wd = reinterpret_cast<float4*>(wsm);
        for (int i = tid; i < NH * NDS / 4; i += DTPB) wd[i] = ws[i];
    }
    __syncthreads();

    int bg = tid & 15, dg = tid >> 4;
    float acc[4][2];
    #pragma unroll
    for (int bi = 0; bi < 4; bi++) { acc[bi][0] = 0.f; acc[bi][1] = 0.f; }
    #pragma unroll 4
    for (int k = 0; k < NH; k++) {
        float4 hv = *reinterpret_cast<const float4*>(&hsm[k * NB + bg * 4]);
        float2 wv = *reinterpret_cast<const float2*>(&wsm[k * NDS + dg * 2]);
        float hvv[4] = {hv.x, hv.y, hv.z, hv.w};
        #pragma unroll
        for (int bi = 0; bi < 4; bi++) {
            acc[bi][0] += hvv[bi] * wv.x;
            acc[bi][1] += hvv[bi] * wv.y;
        }
    }
    float b0 = db[dg * 2], b1 = db[dg * 2 + 1];
    #pragma unroll
    for (int bi = 0; bi < 4; bi++) {
        int b = bg * 4 + bi;
        size_t base = (size_t)b * NT * NDS + (size_t)t * NDS + dg * 2;
        out[base]     = tanhf(acc[bi][0] + b0);
        out[base + 1] = tanhf(acc[bi][1] + b1);
    }
}

#define DENSE_SMEM ((NH * NB + NH * NDS) * 4)

extern "C" void kernel_launch(void* const* d_in, const int* in_sizes, int n_in,
                              void* d_out, int out_size) {
    const float* x    = (const float*)d_in[0];
    const float* wk   = (const float*)d_in[1];
    const float* wr   = (const float*)d_in[2];
    const float* bias = (const float*)d_in[3];
    const float* dw   = (const float*)d_in[4];
    const float* db   = (const float*)d_in[5];
    float* out   = (float*)d_out;
    float* out_h = out + (size_t)NB * NT * NDS;
    float* out_c = out_h + (size_t)NB * NH;

    cudaFuncSetAttribute(xw_kernel,
                         cudaFuncAttributeMaxDynamicSharedMemorySize, XW_SMEM);
    cudaFuncSetAttribute(lstm_kernel,
                         cudaFuncAttributeMaxDynamicSharedMemorySize, LSTM_SMEM);
    cudaFuncSetAttribute(dense_kernel,
                         cudaFuncAttributeMaxDynamicSharedMemorySize, DENSE_SMEM);

    init_kernel<<<64, 256>>>();                          // 0
    wbf_kernel<<<NG4, ND>>>(wk);                         // 1
    xw_kernel<<<NT, 256, XW_SMEM>>>(x, bias);            // 2
    lstm_kernel<<<G, TPB, LSTM_SMEM>>>(wr, out_h, out_c);// 3  <- profiled slot
    dense_kernel<<<NT, DTPB, DENSE_SMEM>>>(dw, db, out); // 4
}

// round 17
// speedup vs baseline: 1.2612x; 1.1264x over previous
#include <cuda_runtime.h>
#include <cuda_bf16.h>
#include <cuda_fp16.h>
#include <cstdint>
#include <math.h>

// ---------------- problem dims ----------------
#define NB 64
#define NT 512
#define ND 128
#define NH 512
#define NDS 32
#define NG4 (4 * NH)   // 2048

// ---------------- LSTM config (R14 structure) ----------------
#define G 128          // persistent CTAs, 1/SM
#define TPB 256        // 8 warps
#define JPC 4          // hidden units per CTA -> 16 true z-cols (m=16, fp16 W)
// SMEM layout (bytes)
#define H_OFF 0                    // h [4 chunks][64 rows][256B] = 65536
#define WS_OFF 65536               // W' staging [16][1024B] = 16384
#define MB_OFF 81920               // 4 mbarriers
#define LSTM_SMEM 81984

__device__ __forceinline__ uint32_t smem_u32(const void* p) {
    uint32_t a;
    asm("{ .reg .u64 t; cvta.to.shared.u64 t, %1; cvt.u32.u64 %0, t; }" : "=r"(a) : "l"(p));
    return a;
}
// fast gate nonlinearities (MUFU-based)
__device__ __forceinline__ float fsig(float x) { return 1.f / (1.f + __expf(-x)); }
__device__ __forceinline__ float ftanh(float x) {
    float ax = fabsf(x);
    float e = __expf(-2.f * ax);
    float r = (1.f - e) / (1.f + e);
    return copysignf(r, x);
}

__device__ __forceinline__ uint4 pack_f16_8(float4 a, float4 b) {
    uint4 r;
    r.x = (uint32_t)__half_as_ushort(__float2half(a.x)) |
          ((uint32_t)__half_as_ushort(__float2half(a.y)) << 16);
    r.y = (uint32_t)__half_as_ushort(__float2half(a.z)) |
          ((uint32_t)__half_as_ushort(__float2half(a.w)) << 16);
    r.z = (uint32_t)__half_as_ushort(__float2half(b.x)) |
          ((uint32_t)__half_as_ushort(__float2half(b.y)) << 16);
    r.w = (uint32_t)__half_as_ushort(__float2half(b.z)) |
          ((uint32_t)__half_as_ushort(__float2half(b.w)) << 16);
    return r;
}

#define LDSM_X4(r0, r1, r2, r3, addr) \
    asm volatile("ldmatrix.sync.aligned.m8n8.x4.shared.b16 {%0,%1,%2,%3}, [%4];" \
        : "=r"(r0), "=r"(r1), "=r"(r2), "=r"(r3) : "r"(addr))

#define MMA_FP16(c, a0, a1, a2, a3, b0, b1) \
    asm volatile("mma.sync.aligned.m16n8k16.row.col.f32.f16.f16.f32 " \
        "{%0,%1,%2,%3}, {%4,%5,%6,%7}, {%8,%9}, {%0,%1,%2,%3};" \
        : "+f"((c)[0]), "+f"((c)[1]), "+f"((c)[2]), "+f"((c)[3]) \
        : "r"(a0), "r"(a1), "r"(a2), "r"(a3), "r"(b0), "r"(b1))

#define CP16(dst, src) \
    asm volatile("cp.async.cg.shared.global [%0], [%1], 16;" :: "r"(dst), "l"(src))
#define CP_COMMIT() asm volatile("cp.async.commit_group;" ::: "memory")
#define CP_WAIT(n)  asm volatile("cp.async.wait_group %0;" :: "n"(n) : "memory")
#define MBARRIER_INIT(mbar, cnt) \
    asm volatile("mbarrier.init.shared.b64 [%0], %1;" :: "r"((uint32_t)(mbar)), "r"((uint32_t)(cnt)) : "memory")
#define MBARRIER_EXPECT_TX(mbar, bytes) \
    asm volatile("mbarrier.arrive.expect_tx.shared.b64 _, [%0], %1;" \
                 :: "r"((uint32_t)(mbar)), "r"((uint32_t)(bytes)) : "memory")
#define BULK_G2S(dst, src, bytes, mbar) \
    asm volatile("cp.async.bulk.shared::cta.global.mbarrier::complete_tx::bytes " \
                 "[%0], [%1], %2, [%3];" \
                 :: "r"((uint32_t)(dst)), "l"(src), "r"((uint32_t)(bytes)), \
                    "r"((uint32_t)(mbar)) : "memory")
#define MBARRIER_WAIT_PARITY(mbar, par) do { \
    uint32_t _m = (uint32_t)(mbar); uint32_t _p = (uint32_t)(par); uint32_t _d; \
    asm volatile("{\n\t.reg .pred p;\n\t" \
        "mbarrier.try_wait.parity.acquire.cta.shared::cta.b64 p, [%1], %2;\n\t" \
        "selp.b32 %0, 1, 0, p;\n\t}" : "=r"(_d) : "r"(_m), "r"(_p) : "memory"); \
    if (!_d) { \
        asm volatile("{\n\t.reg .pred P1;\n\t" \
            "WL_%=:\n\t" \
            "mbarrier.try_wait.parity.acquire.cta.shared::cta.b64 P1, [%0], %1, 0x989680;\n\t" \
            "@P1 bra.uni WD_%=;\n\t" \
            "bra.uni WL_%=;\n\t" \
            "WD_%=:\n\t}" :: "r"(_m), "r"(_p) : "memory"); \
    } } while (0)

// ---------------- global scratch ----------------
// h (fp16) in the exact swizzled SMEM image: [buf][chunk(k128)][row=batch][256B]
__device__ __align__(128) uint8_t g_hb[2][4][64][256];
__device__ __half g_wt[NG4][ND];                // wk transposed (fp16)
__device__ float g_xw[NT][NG4][NB];             // x@Wk + bias, [t][col][b]
__device__ float g_hs[NT][NH][NB];              // hidden states for dense
__device__ unsigned int g_cbar[4 * 32];         // per-chunk monotonic counters

__global__ void init_kernel() {
    int idx = blockIdx.x * blockDim.x + threadIdx.x;
    if (idx < 4 * 32) g_cbar[idx] = 0u;
    uint32_t* p = reinterpret_cast<uint32_t*>(&g_hb[0][0][0][0]);
    for (int i = idx; i < (int)(sizeof(g_hb) / 4); i += gridDim.x * blockDim.x)
        p[i] = 0u;
}

// ---- one-time: transpose + fp16 convert of wk ----
__global__ void wbf_kernel(const float* __restrict__ wk) {
    int n = blockIdx.x;          // 0..2047
    int k = threadIdx.x;         // 0..127
    g_wt[n][k] = __float2half(wk[(size_t)k * NG4 + n]);
}

// =====================================================================
// XW kernel (fp16, 2-stage pipelined B): g_xw[t][col][b] = x@wk + bias
// =====================================================================
#define XA_OFF 0           // [64][256B] = 16384
#define XB_OFF 16384       // 2 stages x 16384 = 32768
#define XZ_OFF 49152       // zb[64][65] f32 = 16640
#define XW_SMEM 65792

__global__ void __launch_bounds__(256, 1) xw_kernel(
    const float* __restrict__ x, const float* __restrict__ bias)
{
    extern __shared__ char smem[];
    const uint32_t sbu = smem_u32(smem);
    float* zb = reinterpret_cast<float*>(smem + XZ_OFF);
    const int tid = threadIdx.x, wid = tid >> 5, lane = tid & 31;
    const int t = blockIdx.x;
    const int s7 = lane & 7;

    // A staging: x fp16, 64 rows (batch) x 256B (k=128)
    for (int i = tid; i < 64 * 16; i += 256) {
        int b = i >> 4, cs = i & 15;
        const float4* xp = reinterpret_cast<const float4*>(
            x + ((size_t)b * NT + t) * ND + cs * 8);
        *reinterpret_cast<uint4*>(smem + XA_OFF + b * 256 + ((cs ^ (b & 7)) << 4))
            = pack_f16_8(xp[0], xp[1]);
    }
    __syncthreads();

    const int mslice = wid & 3, whalf = wid >> 2;
    uint32_t ar[8][4];
    {
        int row8 = ((lane >> 3) & 1) * 8 + s7;
        int acb = lane >> 4;
        #pragma unroll
        for (int ks = 0; ks < 8; ks++) {
            int row = mslice * 16 + row8;
            uint32_t addr = sbu + XA_OFF + row * 256 +
                (((ks * 2 + acb) ^ (row & 7)) << 4);
            LDSM_X4(ar[ks][0], ar[ks][1], ar[ks][2], ar[ks][3], addr);
        }
    }

    const int browl = ((lane >> 4) << 3) + s7;
    const int bcb = (lane >> 3) & 1;

    // prefetch stage 0
    {
        #pragma unroll
        for (int it = 0; it < 4; it++) {
            int i = it * 256 + tid;
            int row = i >> 4, cpi = i & 15;
            const __half* src = &g_wt[row][cpi * 8];
            uint32_t dst = sbu + XB_OFF + row * 256 + ((cpi ^ (row & 7)) << 4);
            CP16(dst, src);
        }
        CP_COMMIT();
    }

    for (int cb = 0; cb < 32; cb++) {
        // prefetch next stage, then wait for current
        if (cb + 1 < 32) {
            uint32_t stg = ((cb + 1) & 1) * 16384;
            #pragma unroll
            for (int it = 0; it < 4; it++) {
                int i = it * 256 + tid;
                int row = i >> 4, cpi = i & 15;
                const __half* src = &g_wt[(cb + 1) * 64 + row][cpi * 8];
                uint32_t dst = sbu + XB_OFF + stg + row * 256 + ((cpi ^ (row & 7)) << 4);
                CP16(dst, src);
            }
            CP_COMMIT();
            CP_WAIT(1);
        } else {
            CP_WAIT(0);
        }
        __syncthreads();

        const uint32_t xb = sbu + XB_OFF + (cb & 1) * 16384;
        float acc[4][4];
        #pragma unroll
        for (int nf = 0; nf < 4; nf++)
            #pragma unroll
            for (int q = 0; q < 4; q++) acc[nf][q] = 0.f;

        #pragma unroll
        for (int ks = 0; ks < 8; ks++) {
            #pragma unroll
            for (int q = 0; q < 2; q++) {
                int rowb = whalf * 32 + q * 16 + browl;
                uint32_t baddr = xb + rowb * 256 + (((ks * 2 + bcb) ^ s7) << 4);
                uint32_t b0, b1, b2, b3;
                LDSM_X4(b0, b1, b2, b3, baddr);
                MMA_FP16(acc[2 * q],     ar[ks][0], ar[ks][1], ar[ks][2], ar[ks][3], b0, b1);
                MMA_FP16(acc[2 * q + 1], ar[ks][0], ar[ks][1], ar[ks][2], ar[ks][3], b2, b3);
            }
        }

        // epilogue -> zb[batch][col]
        #pragma unroll
        for (int nf = 0; nf < 4; nf++) {
            int m = mslice * 16 + (lane >> 2);
            int c = whalf * 32 + (nf >> 1) * 16 + (nf & 1) * 8 + 2 * (lane & 3);
            zb[(size_t)m * 65 + c]           = acc[nf][0];
            zb[(size_t)m * 65 + c + 1]       = acc[nf][1];
            zb[(size_t)(m + 8) * 65 + c]     = acc[nf][2];
            zb[(size_t)(m + 8) * 65 + c + 1] = acc[nf][3];
        }
        __syncthreads();

        // coalesced output: g_xw[t][col][b] contiguous in b
        for (int i = tid; i < 64 * 64; i += 256) {
            int b = i & 63, cl = i >> 6;
            g_xw[t][cb * 64 + cl][b] = zb[(size_t)b * 65 + cl] + bias[cb * 64 + cl];
        }
        __syncthreads();
    }
}

// =====================================================================
// Persistent LSTM (R14 structure, verbatim) — fp16 W (m16), 8 warps x
// (m16 x n8), in-warp gates, 4 mbarriers, CTA-level release publish.
// =====================================================================
__global__ void __launch_bounds__(TPB, 1) lstm_kernel(
    const float* __restrict__ wr,
    float* __restrict__ out_h, float* __restrict__ out_c)
{
    extern __shared__ char smem[];
    const uint32_t sbu = smem_u32(smem);

    const int tid = threadIdx.x;
    const int wid = tid >> 5, lane = tid & 31;
    const int j0 = blockIdx.x * JPC;
    const int s7 = lane & 7;
    const int mychunk = blockIdx.x >> 5;

    if (tid == 0) {
        #pragma unroll
        for (int c = 0; c < 4; c++) MBARRIER_INIT(sbu + MB_OFF + 8 * c, 1);
    }

    // ---- W' staging (fp16): rows m 0-15 = col(gate*4+jj) ----
    for (int i = tid; i < 16 * NH; i += TPB) {
        int m = i & 15, k = i >> 4;
        int gate = m >> 2, jj = m & 3;
        float w = wr[(size_t)k * NG4 + gate * NH + j0 + jj];
        *reinterpret_cast<uint16_t*>(smem + WS_OFF + m * 1024 +
            ((((k >> 3) ^ (m & 7)) << 4) | ((k & 7) << 1))) =
            __half_as_ushort(__float2half(w));
    }
    __syncthreads();

    // ---- a-frags: full k=512, m16 ----
    uint32_t ar[32][4];
    {
        int row = ((lane >> 3) & 1) * 8 + s7;
        int acb = lane >> 4;
        uint32_t rbase = sbu + WS_OFF + row * 1024;
        #pragma unroll
        for (int ks = 0; ks < 32; ks++) {
            int chunk = ks * 2 + acb;
            LDSM_X4(ar[ks][0], ar[ks][1], ar[ks][2], ar[ks][3],
                    rbase + ((chunk ^ (row & 7)) << 4));
        }
    }
    __syncthreads();

    // this thread's gate identity: batch = 8*wid + bl, hidden jj
    const int bl = lane & 7;
    const int jj = lane >> 3;
    const int gb = wid * 8 + bl;
    const int jrow = j0 + jj;
    float c_state = 0.f;

    const int bg4 = lane >> 3;
    const uint32_t bbase = sbu + H_OFF + (wid * 8 + s7) * 256;

    // gate shuffle sources
    const int lsrc1 = jj * 4 + (bl >> 1);
    const int lsrc2 = lsrc1 + 16;
    const bool bodd = (bl & 1) != 0;

    // producer h-write address (pre-swizzled fp16 image)
    const int kq = jrow & 127;
    const size_t poff = (size_t)(jrow >> 7) * 16384 + (size_t)gb * 256 +
                        (((kq >> 3) ^ (gb & 7)) << 4) + (kq & 7) * 2;

    for (int t = 0; t < NT; t++) {
        // prefetch xw (DRAM; consumed at gates)
        float xwv[4];
        #pragma unroll
        for (int g = 0; g < 4; g++)
            xwv[g] = __ldcg(&g_xw[t][g * NH + jrow][gb]);

        const int buf = t & 1;
        // ---- parallel poll + per-chunk bulk copy (warp 0, lanes 0-3) ----
        if (wid == 0 && lane < 4) {
            const unsigned int tgt = 32u * (unsigned int)t;
            const unsigned int* cp = &g_cbar[lane * 32];
            const uint8_t* hsrc = &g_hb[buf][lane][0][0];
            uint32_t mb = sbu + MB_OFF + 8 * lane;
            uint32_t dsts = sbu + H_OFF + lane * 16384;
            bool issued = false;
            for (;;) {
                unsigned int cur;
                asm volatile("ld.global.acquire.gpu.u32 %0, [%1];"
                             : "=r"(cur) : "l"(cp));
                bool ready = cur >= tgt;
                if (ready && !issued) {
                    MBARRIER_EXPECT_TX(mb, 16384);
                    BULK_G2S(dsts, hsrc, 16384, mb);
                    issued = true;
                }
                if (__all_sync(0x0000000Fu, ready)) break;
            }
        }

        float acc[4];
        acc[0] = acc[1] = acc[2] = acc[3] = 0.f;

        // ---- chunk-ordered MMA: per kk2 one LDSM.x4 (n8 k32) + 2 MMA ----
        #pragma unroll
        for (int c = 0; c < 4; c++) {
            MBARRIER_WAIT_PARITY(sbu + MB_OFF + 8 * c, t & 1);
            uint32_t base0 = bbase + c * 16384;
            #pragma unroll
            for (int kk2 = 0; kk2 < 4; kk2++) {
                int ks = c * 8 + kk2 * 2;
                uint32_t off = (((kk2 * 4 + bg4) ^ s7) << 4);
                uint32_t b0, b1, b2, b3;
                LDSM_X4(b0, b1, b2, b3, base0 + off);
                MMA_FP16(acc, ar[ks][0],     ar[ks][1],     ar[ks][2],     ar[ks][3],     b0, b1);
                MMA_FP16(acc, ar[ks + 1][0], ar[ks + 1][1], ar[ks + 1][2], ar[ks + 1][3], b2, b3);
            }
        }

        // ---- gates fully in-warp: 8 shuffles transpose the z tile ----
        float hv;
        {
            float v0 = __shfl_sync(0xffffffffu, acc[0], lsrc1);
            float v1 = __shfl_sync(0xffffffffu, acc[1], lsrc1);
            float v2 = __shfl_sync(0xffffffffu, acc[2], lsrc1);
            float v3 = __shfl_sync(0xffffffffu, acc[3], lsrc1);
            float w0 = __shfl_sync(0xffffffffu, acc[0], lsrc2);
            float w1 = __shfl_sync(0xffffffffu, acc[1], lsrc2);
            float w2 = __shfl_sync(0xffffffffu, acc[2], lsrc2);
            float w3 = __shfl_sync(0xffffffffu, acc[3], lsrc2);
            float z0 = xwv[0] + (bodd ? v1 : v0);
            float z1 = xwv[1] + (bodd ? w1 : w0);
            float z2 = xwv[2] + (bodd ? v3 : v2);
            float z3 = xwv[3] + (bodd ? w3 : w2);

            float ig = fsig(z0);
            float fg = fsig(z1);
            float gv = ftanh(z2);
            float og = fsig(z3);
            c_state = fg * c_state + ig * gv;
            hv = og * ftanh(c_state);
            uint8_t* hdst = &g_hb[(t + 1) & 1][0][0][0];
            *reinterpret_cast<uint16_t*>(hdst + poff) =
                __half_as_ushort(__float2half(hv));
        }
        __syncthreads();

        // ---- publish (release atomic covers all h stores via syncthreads) ----
        if (t < NT - 1 && tid == 0) {
            asm volatile("red.release.gpu.global.add.u32 [%0], %1;"
                         :: "l"(&g_cbar[mychunk * 32]), "r"(1u) : "memory");
        }

        // ---- off-critical-path: hs store for dense + final outputs ----
        g_hs[t][jrow][gb] = hv;
        if (t == NT - 1) {
            out_h[(size_t)gb * NH + jrow] = hv;
            out_c[(size_t)gb * NH + jrow] = c_state;
        }
    }
}

// ---------------- Dense(32, tanh) over all timesteps ----------------
#define DTPB 256
__global__ void __launch_bounds__(DTPB, 1) dense_kernel(
    const float* __restrict__ dw, const float* __restrict__ db,
    float* __restrict__ out)
{
    extern __shared__ float smemf[];
    float* hsm = smemf;
    float* wsm = smemf + NH * NB;
    int t = blockIdx.x, tid = threadIdx.x;
    {
        const float4* src = reinterpret_cast<const float4*>(&g_hs[t][0][0]);
        float4* dst = reinterpret_cast<float4*>(hsm);
        for (int i = tid; i < NH * NB / 4; i += DTPB) dst[i] = src[i];
        const float4* ws = reinterpret_cast<const float4*>(dw);
        float4* wd = reinterpret_cast<float4*>(wsm);
        for (int i = tid; i < NH * NDS / 4; i += DTPB) wd[i] = ws[i];
    }
    __syncthreads();

    int bg = tid & 15, dg = tid >> 4;
    float acc[4][2];
    #pragma unroll
    for (int bi = 0; bi < 4; bi++) { acc[bi][0] = 0.f; acc[bi][1] = 0.f; }
    #pragma unroll 4
    for (int k = 0; k < NH; k++) {
        float4 hv = *reinterpret_cast<const float4*>(&hsm[k * NB + bg * 4]);
        float2 wv = *reinterpret_cast<const float2*>(&wsm[k * NDS + dg * 2]);
        float hvv[4] = {hv.x, hv.y, hv.z, hv.w};
        #pragma unroll
        for (int bi = 0; bi < 4; bi++) {
            acc[bi][0] += hvv[bi] * wv.x;
            acc[bi][1] += hvv[bi] * wv.y;
        }
    }
    float b0 = db[dg * 2], b1 = db[dg * 2 + 1];
    #pragma unroll
    for (int bi = 0; bi < 4; bi++) {
        int b = bg * 4 + bi;
        size_t base = (size_t)b * NT * NDS + (size_t)t * NDS + dg * 2;
        out[base]     = tanhf(acc[bi][0] + b0);
        out[base + 1] = tanhf(acc[bi][1] + b1);
    }
}

#define DENSE_SMEM ((NH * NB + NH * NDS) * 4)

extern "C" void kernel_launch(void* const* d_in, const int* in_sizes, int n_in,
                              void* d_out, int out_size) {
    const float* x    = (const float*)d_in[0];
    const float* wk   = (const float*)d_in[1];
    const float* wr   = (const float*)d_in[2];
    const float* bias = (const float*)d_in[3];
    const float* dw   = (const float*)d_in[4];
    const float* db   = (const float*)d_in[5];
    float* out   = (float*)d_out;
    float* out_h = out + (size_t)NB * NT * NDS;
    float* out_c = out_h + (size_t)NB * NH;

    cudaFuncSetAttribute(xw_kernel,
                         cudaFuncAttributeMaxDynamicSharedMemorySize, XW_SMEM);
    cudaFuncSetAttribute(lstm_kernel,
                         cudaFuncAttributeMaxDynamicSharedMemorySize, LSTM_SMEM);
    cudaFuncSetAttribute(dense_kernel,
                         cudaFuncAttributeMaxDynamicSharedMemorySize, DENSE_SMEM);

    init_kernel<<<64, 256>>>();                          // 0
    wbf_kernel<<<NG4, ND>>>(wk);                         // 1
    xw_kernel<<<NT, 256, XW_SMEM>>>(x, bias);            // 2
    lstm_kernel<<<G, TPB, LSTM_SMEM>>>(wr, out_h, out_c);// 3  <- profiled slot
    dense_kernel<<<NT, DTPB, DENSE_SMEM>>>(dw, db, out); // 4
}